// round 1
// baseline (speedup 1.0000x reference)
#include <cuda_runtime.h>
#include <math.h>

#define N_BODY 512
#define NV 6890
#define NJ 24
#define NP 207

__device__ __constant__ int d_parents[NJ] =
    {0, 0, 0, 0, 1, 2, 3, 4, 5, 6, 7, 8, 9, 9, 9, 12, 13, 14, 16, 17, 18, 19, 20, 21};

// ---------------- scratch (device globals; no allocations) ----------------
__device__ float g_JT[NJ * 3];            // J_regressor @ v_template
__device__ float g_JS[NJ * 30];           // J_regressor @ shapedirs  [j][c][k]
__device__ float g_jregT[NJ * NV];        // joint_regressor transposed [j][v]
__device__ float g_lrotT[NP * N_BODY];    // lrotmin transposed [p][n]
__device__ float g_GT[NJ * 12 * N_BODY];  // G' (3x4 row-major) transposed [j*12+e][n]
__device__ float g_betasT[10 * N_BODY];
__device__ float g_transT[3 * N_BODY];

// ---------------- kernel 1: reduce J_regressor against template/shapedirs ----------------
__global__ void k_pre(const float* __restrict__ Jreg,
                      const float* __restrict__ vt,
                      const float* __restrict__ sd) {
    int j = blockIdx.x;
    float acc[33];
#pragma unroll
    for (int i = 0; i < 33; i++) acc[i] = 0.f;
    for (int v = threadIdx.x; v < NV; v += blockDim.x) {
        float r = Jreg[j * NV + v];
#pragma unroll
        for (int c = 0; c < 3; c++) acc[c] += r * vt[v * 3 + c];
#pragma unroll
        for (int i = 0; i < 30; i++) acc[3 + i] += r * sd[v * 30 + i];
    }
    __shared__ float red[256];
    for (int i = 0; i < 33; i++) {
        red[threadIdx.x] = acc[i];
        __syncthreads();
        for (int s = 128; s > 0; s >>= 1) {
            if (threadIdx.x < s) red[threadIdx.x] += red[threadIdx.x + s];
            __syncthreads();
        }
        if (threadIdx.x == 0) {
            if (i < 3) g_JT[j * 3 + i] = red[0];
            else       g_JS[j * 30 + (i - 3)] = red[0];
        }
        __syncthreads();
    }
}

// ---------------- kernel 2: transpose joint_regressor ----------------
__global__ void k_jregT(const float* __restrict__ jreg) {
    int v = blockIdx.x * blockDim.x + threadIdx.x;
    if (v < NV) {
#pragma unroll
        for (int j = 0; j < NJ; j++) g_jregT[j * NV + v] = jreg[v * NJ + j];
    }
}

// ---------------- kernel 3: per-body rodrigues + FK + lrotmin ----------------
__global__ void k_body(const float* __restrict__ betas,
                       const float* __restrict__ thetas,
                       const float* __restrict__ trans) {
    int n = blockIdx.x;
    int lane = threadIdx.x;
    __shared__ float sR[NJ][9];
    __shared__ float sJ[NJ][3];
    __shared__ float sT[NJ][3];
    __shared__ float sG[NJ][12];  // 3x4 row-major, col 3 = translation

    if (lane < NJ) {
        int j = lane;
        float b[10];
#pragma unroll
        for (int k = 0; k < 10; k++) b[k] = betas[n * 10 + k];
#pragma unroll
        for (int c = 0; c < 3; c++) {
            float a = g_JT[j * 3 + c];
#pragma unroll
            for (int k = 0; k < 10; k++) a += g_JS[j * 30 + c * 10 + k] * b[k];
            sJ[j][c] = a;
        }
        float rx = thetas[n * 72 + j * 3 + 0];
        float ry = thetas[n * 72 + j * 3 + 1];
        float rz = thetas[n * 72 + j * 3 + 2];
        float th = sqrtf(rx * rx + ry * ry + rz * rz) + 1e-8f;
        float inv = 1.0f / th;
        float x = rx * inv, y = ry * inv, z = rz * inv;
        float ct = cosf(th), st = sinf(th), oc = 1.0f - ct;
        sR[j][0] = ct + oc * x * x;      sR[j][1] = oc * x * y - st * z;  sR[j][2] = oc * x * z + st * y;
        sR[j][3] = oc * y * x + st * z;  sR[j][4] = ct + oc * y * y;      sR[j][5] = oc * y * z - st * x;
        sR[j][6] = oc * z * x - st * y;  sR[j][7] = oc * z * y + st * x;  sR[j][8] = ct + oc * z * z;
    }
    __syncwarp();
    if (lane < NJ) {
        int j = lane;
        if (j == 0) {
#pragma unroll
            for (int c = 0; c < 3; c++) sT[0][c] = sJ[0][c];
        } else {
            int p = d_parents[j];
#pragma unroll
            for (int c = 0; c < 3; c++) sT[j][c] = sJ[j][c] - sJ[p][c];
        }
    }
    __syncwarp();
    if (lane == 0) {
        // forward kinematics (sequential, topologically ordered parents)
#pragma unroll
        for (int r = 0; r < 3; r++) {
            sG[0][r * 4 + 0] = sR[0][r * 3 + 0];
            sG[0][r * 4 + 1] = sR[0][r * 3 + 1];
            sG[0][r * 4 + 2] = sR[0][r * 3 + 2];
            sG[0][r * 4 + 3] = sT[0][r];
        }
        for (int j = 1; j < NJ; j++) {
            int p = d_parents[j];
            float Rn[9], tn[3];
#pragma unroll
            for (int r = 0; r < 3; r++) {
#pragma unroll
                for (int c = 0; c < 3; c++) {
                    Rn[r * 3 + c] = sG[p][r * 4 + 0] * sR[j][0 * 3 + c]
                                  + sG[p][r * 4 + 1] * sR[j][1 * 3 + c]
                                  + sG[p][r * 4 + 2] * sR[j][2 * 3 + c];
                }
                tn[r] = sG[p][r * 4 + 3]
                      + sG[p][r * 4 + 0] * sT[j][0]
                      + sG[p][r * 4 + 1] * sT[j][1]
                      + sG[p][r * 4 + 2] * sT[j][2];
            }
#pragma unroll
            for (int r = 0; r < 3; r++) {
                sG[j][r * 4 + 0] = Rn[r * 3 + 0];
                sG[j][r * 4 + 1] = Rn[r * 3 + 1];
                sG[j][r * 4 + 2] = Rn[r * 3 + 2];
                sG[j][r * 4 + 3] = tn[r];
            }
        }
    }
    __syncwarp();
    if (lane < NJ) {
        int j = lane;
        // remove rest-pose joint location: t' = t - R*J
        float t0 = sG[j][3]  - (sG[j][0] * sJ[j][0] + sG[j][1] * sJ[j][1] + sG[j][2]  * sJ[j][2]);
        float t1 = sG[j][7]  - (sG[j][4] * sJ[j][0] + sG[j][5] * sJ[j][1] + sG[j][6]  * sJ[j][2]);
        float t2 = sG[j][11] - (sG[j][8] * sJ[j][0] + sG[j][9] * sJ[j][1] + sG[j][10] * sJ[j][2]);
        sG[j][3] = t0; sG[j][7] = t1; sG[j][11] = t2;
    }
    __syncwarp();
    for (int idx = lane; idx < NJ * 12; idx += 32)
        g_GT[idx * N_BODY + n] = sG[idx / 12][idx % 12];
    for (int idx = lane; idx < NP; idx += 32) {
        int j = idx / 9 + 1;
        int e = idx % 9;
        float v = sR[j][e];
        if (e == 0 || e == 4 || e == 8) v -= 1.0f;
        g_lrotT[idx * N_BODY + n] = v;
    }
    if (lane < 10) g_betasT[lane * N_BODY + n] = betas[n * 10 + lane];
    if (lane < 3)  g_transT[lane * N_BODY + n] = trans[n * 3 + lane];
}

// ---------------- kernel 4: fused shape blend + pose blend + LBS ----------------
// tile: 64 bodies x 16 verts, 128 threads: thread = 1 body x 8 verts
#define TN 64
#define TV 16
#define PD_PAD 52  // 48 used floats per p, padded to 52 (16B-aligned rows, reduced store conflicts)

__global__ void __launch_bounds__(128) k_main(const float* __restrict__ vt,
                                              const float* __restrict__ sd,
                                              const float* __restrict__ pd,
                                              const float* __restrict__ w,
                                              float* __restrict__ out) {
    extern __shared__ float sm[];
    float* lrot_s = sm;                       // NP * TN
    float* pd_s   = lrot_s + NP * TN;         // NP * PD_PAD (p-major)
    float* w_s    = pd_s + NP * PD_PAD;       // TV * 24
    float* sd_s   = w_s + TV * 24;            // TV * 30
    float* vt_s   = sd_s + TV * 30;           // TV * 3

    int tid = threadIdx.x;
    int nbase = blockIdx.x * TN;
    int vbase = blockIdx.y * TV;

    // load lrotmin slice: [p][n_local], coalesced
    for (int i = tid; i < NP * TN; i += 128) {
        int p = i >> 6, nl = i & 63;
        lrot_s[i] = g_lrotT[p * N_BODY + nbase + nl];
    }
    // load posedirs tile, transposed to p-major: pd_s[p*PD_PAD + vl*3 + c]
    for (int i = tid; i < 48 * NP; i += 128) {
        int f = i / NP, p = i % NP;   // consecutive threads -> consecutive p (coalesced gmem)
        int vl = f / 3, c = f % 3;
        int v = vbase + vl;
        pd_s[p * PD_PAD + f] = (v < NV) ? pd[(size_t)v * 621 + c * 207 + p] : 0.f;
    }
    for (int i = tid; i < TV * 24; i += 128) {
        int vl = i / 24, j = i % 24;
        int v = vbase + vl;
        w_s[i] = (v < NV) ? w[v * 24 + j] : 0.f;
    }
    for (int i = tid; i < TV * 30; i += 128) {
        int vl = i / 30, f = i % 30;
        int v = vbase + vl;
        sd_s[i] = (v < NV) ? sd[v * 30 + f] : 0.f;
    }
    for (int i = tid; i < TV * 3; i += 128) {
        int vl = i / 3, c = i % 3;
        int v = vbase + vl;
        vt_s[i] = (v < NV) ? vt[v * 3 + c] : 0.f;
    }
    __syncthreads();

    int nl = tid & 63;
    int vg = tid >> 6;  // 0 or 1: which 8-vertex group
    int n = nbase + nl;

    // v_shaped for my 8 verts
    float b[10];
#pragma unroll
    for (int k = 0; k < 10; k++) b[k] = g_betasT[k * N_BODY + n];
    float accp[24];
#pragma unroll
    for (int vi = 0; vi < 8; vi++) {
        int vl = vg * 8 + vi;
#pragma unroll
        for (int c = 0; c < 3; c++) {
            float a = vt_s[vl * 3 + c];
#pragma unroll
            for (int k = 0; k < 10; k++) a += b[k] * sd_s[vl * 30 + c * 10 + k];
            accp[vi * 3 + c] = a;
        }
    }

    // pose blend: accp += sum_p lrot[p] * posedirs[v,c,p]
    const float4* pd4 = reinterpret_cast<const float4*>(pd_s);
#pragma unroll 3
    for (int p = 0; p < NP; p++) {
        float lr = lrot_s[p * TN + nl];
        int base = p * (PD_PAD / 4) + vg * 6;
        float4 q0 = pd4[base + 0];
        float4 q1 = pd4[base + 1];
        float4 q2 = pd4[base + 2];
        float4 q3 = pd4[base + 3];
        float4 q4 = pd4[base + 4];
        float4 q5 = pd4[base + 5];
        accp[0]  += lr * q0.x; accp[1]  += lr * q0.y; accp[2]  += lr * q0.z; accp[3]  += lr * q0.w;
        accp[4]  += lr * q1.x; accp[5]  += lr * q1.y; accp[6]  += lr * q1.z; accp[7]  += lr * q1.w;
        accp[8]  += lr * q2.x; accp[9]  += lr * q2.y; accp[10] += lr * q2.z; accp[11] += lr * q2.w;
        accp[12] += lr * q3.x; accp[13] += lr * q3.y; accp[14] += lr * q3.z; accp[15] += lr * q3.w;
        accp[16] += lr * q4.x; accp[17] += lr * q4.y; accp[18] += lr * q4.z; accp[19] += lr * q4.w;
        accp[20] += lr * q5.x; accp[21] += lr * q5.y; accp[22] += lr * q5.z; accp[23] += lr * q5.w;
    }

    // skinning: out = sum_j w[v,j] * (G'_j [vp;1]) + trans
    float outp[24];
    float t0 = g_transT[0 * N_BODY + n];
    float t1 = g_transT[1 * N_BODY + n];
    float t2 = g_transT[2 * N_BODY + n];
#pragma unroll
    for (int vi = 0; vi < 8; vi++) {
        outp[vi * 3 + 0] = t0; outp[vi * 3 + 1] = t1; outp[vi * 3 + 2] = t2;
    }
#pragma unroll 2
    for (int j = 0; j < NJ; j++) {
        float g[12];
#pragma unroll
        for (int e = 0; e < 12; e++) g[e] = g_GT[(j * 12 + e) * N_BODY + n];
#pragma unroll
        for (int vi = 0; vi < 8; vi++) {
            float vx = accp[vi * 3 + 0];
            float vy = accp[vi * 3 + 1];
            float vz = accp[vi * 3 + 2];
            float ww = w_s[(vg * 8 + vi) * 24 + j];
            outp[vi * 3 + 0] += ww * (g[0] * vx + g[1] * vy + g[2]  * vz + g[3]);
            outp[vi * 3 + 1] += ww * (g[4] * vx + g[5] * vy + g[6]  * vz + g[7]);
            outp[vi * 3 + 2] += ww * (g[8] * vx + g[9] * vy + g[10] * vz + g[11]);
        }
    }

#pragma unroll
    for (int vi = 0; vi < 8; vi++) {
        int v = vbase + vg * 8 + vi;
        if (v < NV) {
            size_t o = ((size_t)n * NV + v) * 3;
            out[o + 0] = outp[vi * 3 + 0];
            out[o + 1] = outp[vi * 3 + 1];
            out[o + 2] = outp[vi * 3 + 2];
        }
    }
}

// ---------------- kernel 5: joint regression of the result ----------------
__global__ void __launch_bounds__(256) k_joints(const float* __restrict__ res,
                                                float* __restrict__ jout) {
    int n = blockIdx.x;
    int tid = threadIdx.x;
    float acc[72];
#pragma unroll
    for (int i = 0; i < 72; i++) acc[i] = 0.f;
    for (int v = tid; v < NV; v += 256) {
        size_t o = ((size_t)n * NV + v) * 3;
        float r0 = res[o + 0], r1 = res[o + 1], r2 = res[o + 2];
#pragma unroll
        for (int j = 0; j < NJ; j++) {
            float jr = g_jregT[j * NV + v];
            acc[j * 3 + 0] += jr * r0;
            acc[j * 3 + 1] += jr * r1;
            acc[j * 3 + 2] += jr * r2;
        }
    }
#pragma unroll
    for (int i = 0; i < 72; i++) {
#pragma unroll
        for (int off = 16; off > 0; off >>= 1)
            acc[i] += __shfl_down_sync(0xffffffff, acc[i], off);
    }
    __shared__ float red[8][72];
    int wid = tid >> 5, lanei = tid & 31;
    if (lanei == 0) {
#pragma unroll
        for (int i = 0; i < 72; i++) red[wid][i] = acc[i];
    }
    __syncthreads();
    if (tid < 72) {
        float s = 0.f;
#pragma unroll
        for (int wq = 0; wq < 8; wq++) s += red[wq][tid];
        jout[n * 72 + tid] = s;
    }
}

// ---------------- launch ----------------
extern "C" void kernel_launch(void* const* d_in, const int* in_sizes, int n_in,
                              void* d_out, int out_size) {
    const float* betas  = (const float*)d_in[0];
    const float* thetas = (const float*)d_in[1];
    const float* trans  = (const float*)d_in[2];
    const float* vt     = (const float*)d_in[3];
    const float* sd     = (const float*)d_in[4];
    const float* pd     = (const float*)d_in[5];
    const float* Jreg   = (const float*)d_in[6];
    const float* jreg   = (const float*)d_in[7];
    const float* w      = (const float*)d_in[8];
    float* out  = (float*)d_out;
    float* jout = out + (size_t)N_BODY * NV * 3;

    k_pre<<<NJ, 256>>>(Jreg, vt, sd);
    k_jregT<<<(NV + 255) / 256, 256>>>(jreg);
    k_body<<<N_BODY, 32>>>(betas, thetas, trans);

    const int SMEM = (NP * TN + NP * PD_PAD + TV * 24 + TV * 30 + TV * 3) * (int)sizeof(float);
    cudaFuncSetAttribute(k_main, cudaFuncAttributeMaxDynamicSharedMemorySize, SMEM);
    dim3 grid(N_BODY / TN, (NV + TV - 1) / TV);
    k_main<<<grid, 128, SMEM>>>(vt, sd, pd, w, out);

    k_joints<<<N_BODY, 256>>>(out, jout);
}